// round 2
// baseline (speedup 1.0000x reference)
#include <cuda_runtime.h>
#include <cuda_bf16.h>
#include <cstdint>

// Problem constants (fixed by the dataset)
#define BATCH   8192
#define SEQ     8
#define HID     2048
#define NEXP    64
#define TOPK    8
#define ROWSTR  (SEQ * HID)      // 16384 floats between consecutive b at s=0

// GEMM tiling
#define BM 128
#define BN 64
#define BK 16
#define SPLITS 4
#define KSPLIT (HID / SPLITS)    // 512
#define NSTAGE (KSPLIT / BK)     // 32

// Scratch (device globals — no allocation allowed)
__device__ float g_partial[SPLITS][BATCH * NEXP];  // 8 MB
__device__ float g_imp[NEXP];
__device__ int   g_cnt[NEXP];

// ---------------------------------------------------------------------------
// Kernel 1: zero the small accumulators (graph replays must start clean)
// ---------------------------------------------------------------------------
__global__ void init_kernel() {
    int t = threadIdx.x;
    if (t < NEXP) { g_imp[t] = 0.0f; g_cnt[t] = 0; }
}

// ---------------------------------------------------------------------------
// Kernel 2: logits GEMM. A = hidden_states[:,0,:] (row stride 16384),
// B = gate_w [64,2048] (transposed on the fly into smem [k][n]).
// f32x2 packed FMA accumulators, double-buffered smem, split-K=4.
// ---------------------------------------------------------------------------
__global__ void __launch_bounds__(128, 2)
gemm_kernel(const float* __restrict__ hs, const float* __restrict__ gw) {
    __shared__ __align__(16) float As[2][BK][BM];
    __shared__ __align__(16) float Bs[2][BK][BN];

    const int t  = threadIdx.x;          // 0..127
    const int m0 = blockIdx.x * BM;
    const int sp = blockIdx.y;
    const int k0 = sp * KSPLIT;

    const int ty   = t >> 3;             // 0..15
    const int tx   = t & 7;              // 0..7
    const int row0 = ty * 8;
    const int col0 = tx * 8;

    // A: thread t owns global row (m0+t); loads 16 floats (4x float4) per stage
    const float* aptr = hs + (size_t)(m0 + t) * ROWSTR + k0;
    // B: thread t loads expert bn, k-groups {bg, bg+2}
    const int bn = t & 63;
    const int bg = t >> 6;               // 0 or 1
    const float* bptr = gw + (size_t)bn * HID + k0;

    float4 ar[4];
    float4 br[2];

    // ---- prefetch stage 0 ----
#pragma unroll
    for (int kk = 0; kk < 4; kk++) ar[kk] = *(const float4*)(aptr + kk * 4);
    br[0] = *(const float4*)(bptr + bg * 4);
    br[1] = *(const float4*)(bptr + (bg + 2) * 4);

#pragma unroll
    for (int kk = 0; kk < 4; kk++) {
        As[0][kk * 4 + 0][t] = ar[kk].x;
        As[0][kk * 4 + 1][t] = ar[kk].y;
        As[0][kk * 4 + 2][t] = ar[kk].z;
        As[0][kk * 4 + 3][t] = ar[kk].w;
    }
    {
        Bs[0][bg * 4 + 0][bn] = br[0].x;
        Bs[0][bg * 4 + 1][bn] = br[0].y;
        Bs[0][bg * 4 + 2][bn] = br[0].z;
        Bs[0][bg * 4 + 3][bn] = br[0].w;
        int g2 = bg + 2;
        Bs[0][g2 * 4 + 0][bn] = br[1].x;
        Bs[0][g2 * 4 + 1][bn] = br[1].y;
        Bs[0][g2 * 4 + 2][bn] = br[1].z;
        Bs[0][g2 * 4 + 3][bn] = br[1].w;
    }
    __syncthreads();

    unsigned long long acc[8][4];
#pragma unroll
    for (int i = 0; i < 8; i++)
#pragma unroll
        for (int j = 0; j < 4; j++) acc[i][j] = 0ULL;

    for (int s = 0; s < NSTAGE; s++) {
        const int cur = s & 1;

        // issue next-stage global loads early (hidden behind compute)
        if (s + 1 < NSTAGE) {
            const float* ap = aptr + (size_t)(s + 1) * BK;
#pragma unroll
            for (int kk = 0; kk < 4; kk++) ar[kk] = *(const float4*)(ap + kk * 4);
            const float* bp = bptr + (size_t)(s + 1) * BK;
            br[0] = *(const float4*)(bp + bg * 4);
            br[1] = *(const float4*)(bp + (bg + 2) * 4);
        }

        // compute current stage
#pragma unroll
        for (int k = 0; k < BK; k++) {
            float4 a0 = *(const float4*)&As[cur][k][row0];
            float4 a1 = *(const float4*)&As[cur][k][row0 + 4];
            ulonglong2 b0 = *(const ulonglong2*)&Bs[cur][k][col0];
            ulonglong2 b1 = *(const ulonglong2*)&Bs[cur][k][col0 + 4];

            float av[8] = {a0.x, a0.y, a0.z, a0.w, a1.x, a1.y, a1.z, a1.w};
            unsigned long long bv[4] = {b0.x, b0.y, b1.x, b1.y};

#pragma unroll
            for (int i = 0; i < 8; i++) {
                unsigned long long a2;
                asm("mov.b64 %0, {%1, %1};" : "=l"(a2) : "f"(av[i]));
#pragma unroll
                for (int j = 0; j < 4; j++) {
                    asm("fma.rn.f32x2 %0, %1, %2, %0;"
                        : "+l"(acc[i][j]) : "l"(a2), "l"(bv[j]));
                }
            }
        }

        // store next stage into the other buffer
        if (s + 1 < NSTAGE) {
            const int nxt = cur ^ 1;
#pragma unroll
            for (int kk = 0; kk < 4; kk++) {
                As[nxt][kk * 4 + 0][t] = ar[kk].x;
                As[nxt][kk * 4 + 1][t] = ar[kk].y;
                As[nxt][kk * 4 + 2][t] = ar[kk].z;
                As[nxt][kk * 4 + 3][t] = ar[kk].w;
            }
            Bs[nxt][bg * 4 + 0][bn] = br[0].x;
            Bs[nxt][bg * 4 + 1][bn] = br[0].y;
            Bs[nxt][bg * 4 + 2][bn] = br[0].z;
            Bs[nxt][bg * 4 + 3][bn] = br[0].w;
            int g2 = bg + 2;
            Bs[nxt][g2 * 4 + 0][bn] = br[1].x;
            Bs[nxt][g2 * 4 + 1][bn] = br[1].y;
            Bs[nxt][g2 * 4 + 2][bn] = br[1].z;
            Bs[nxt][g2 * 4 + 3][bn] = br[1].w;
            __syncthreads();
        }
    }

    // epilogue: 64-bit stores of packed pairs
#pragma unroll
    for (int i = 0; i < 8; i++) {
        float* op = &g_partial[sp][(size_t)(m0 + row0 + i) * NEXP + col0];
#pragma unroll
        for (int j = 0; j < 4; j++) {
            ((unsigned long long*)op)[j] = acc[i][j];
        }
    }
}

// ---------------------------------------------------------------------------
// Kernel 3: warp-per-row softmax + top-8 + weights + importance/load counts.
// Lane l owns experts l and l+32. Output layout:
//   out[0 .. B*8)          topk_idx (as float)
//   out[B*8 .. 2*B*8)      topk_weights
//   out[2*B*8]             aux_loss (written by finalize)
// ---------------------------------------------------------------------------
__global__ void __launch_bounds__(256)
router_kernel(float* __restrict__ out) {
    __shared__ float s_imp[NEXP];
    __shared__ int   s_cnt[NEXP];
    const int tid = threadIdx.x;
    if (tid < NEXP) { s_imp[tid] = 0.0f; s_cnt[tid] = 0; }
    __syncthreads();

    const int lane = tid & 31;
    const int row  = (blockIdx.x * blockDim.x + tid) >> 5;  // grid sized exactly

    // sum split-K partials
    float l0 = 0.0f, l1 = 0.0f;
#pragma unroll
    for (int sp = 0; sp < SPLITS; sp++) {
        const float* p = &g_partial[sp][(size_t)row * NEXP];
        l0 += p[lane];
        l1 += p[lane + 32];
    }

    // softmax over 64
    float m = fmaxf(l0, l1);
#pragma unroll
    for (int off = 16; off; off >>= 1)
        m = fmaxf(m, __shfl_xor_sync(0xffffffffu, m, off));
    float p0 = __expf(l0 - m);
    float p1 = __expf(l1 - m);
    float sm = p0 + p1;
#pragma unroll
    for (int off = 16; off; off >>= 1)
        sm += __shfl_xor_sync(0xffffffffu, sm, off);
    float inv = 1.0f / sm;
    p0 *= inv;
    p1 *= inv;

    // importance accumulation (block-staged)
    atomicAdd(&s_imp[lane], p0);
    atomicAdd(&s_imp[lane + 32], p1);

    // top-8 via iterated warp argmax (tie -> smaller index, matches lax.top_k)
    bool sel0 = false, sel1 = false;
    float wsum = 0.0f, myv = 0.0f;
    int myi = 0;
#pragma unroll
    for (int it = 0; it < TOPK; it++) {
        float cv = sel0 ? -1.0f : p0;   // probs are > 0
        int   ci = lane;
        if (!sel1 && p1 > cv) { cv = p1; ci = lane + 32; }
#pragma unroll
        for (int off = 16; off; off >>= 1) {
            float ov = __shfl_xor_sync(0xffffffffu, cv, off);
            int   oi = __shfl_xor_sync(0xffffffffu, ci, off);
            if (ov > cv || (ov == cv && oi < ci)) { cv = ov; ci = oi; }
        }
        wsum += cv;
        if (ci == lane)           sel0 = true;
        else if (ci == lane + 32) sel1 = true;
        if (lane == it) { myv = cv; myi = ci; }
        if (lane == 0)  atomicAdd(&s_cnt[ci], 1);
    }

    float invw = 1.0f / fmaxf(wsum, 1e-8f);
    if (lane < TOPK) {
        out[(size_t)row * TOPK + lane] = (float)myi;
        out[(size_t)BATCH * TOPK + (size_t)row * TOPK + lane] = myv * invw;
    }

    __syncthreads();
    if (tid < NEXP) {
        atomicAdd(&g_imp[tid], s_imp[tid]);
        atomicAdd(&g_cnt[tid], s_cnt[tid]);
    }
}

// ---------------------------------------------------------------------------
// Kernel 4: aux loss = sum_e E * (imp_e/B) * (cnt_e/(B*K))
// ---------------------------------------------------------------------------
__global__ void finalize_kernel(float* __restrict__ out) {
    __shared__ float red[NEXP];
    int t = threadIdx.x;
    float v = (float)NEXP * (g_imp[t] / (float)BATCH) *
              ((float)g_cnt[t] / (float)(BATCH * TOPK));
    red[t] = v;
    __syncthreads();
    if (t == 0) {
        float s = 0.0f;
#pragma unroll
        for (int i = 0; i < NEXP; i++) s += red[i];
        out[(size_t)2 * BATCH * TOPK] = s;
    }
}

// ---------------------------------------------------------------------------
extern "C" void kernel_launch(void* const* d_in, const int* in_sizes, int n_in,
                              void* d_out, int out_size) {
    const float* hs  = (const float*)d_in[0];   // [8192, 8, 2048] f32
    const float* gw  = (const float*)d_in[1];   // [64, 2048] f32
    float*       out = (float*)d_out;           // 131073 f32

    init_kernel<<<1, 64>>>();
    gemm_kernel<<<dim3(BATCH / BM, SPLITS), 128>>>(hs, gw);
    router_kernel<<<(BATCH * 32) / 256, 256>>>(out);
    finalize_kernel<<<1, 64>>>(out);
}

// round 4
// speedup vs baseline: 1.4837x; 1.4837x over previous
#include <cuda_runtime.h>
#include <cuda_bf16.h>
#include <cstdint>

// ---------------------------------------------------------------------------
// Problem constants
// ---------------------------------------------------------------------------
#define BATCH   8192
#define SEQ     8
#define HID     2048
#define NEXP    64
#define TOPK    8
#define ROWSTR  (SEQ * HID)

// GEMM config
#define BM      128
#define KT      64                 // k-tile (f32 elements)
#define KSPL    2
#define KHALF   (HID / KSPL)       // 1024
#define NT      (KHALF / KT)       // 16 tiles per split

// smem plane sizes (bf16, 128B per row)
#define A_PL    16384              // 128 rows x 128B
#define B_PL    8192               // 64 rows x 128B
#define ABUF    (3 * A_PL)         // 3 split planes
#define BBUF    (3 * B_PL)
#define STAGE   (ABUF + BBUF)      // 73728
#define SM_ALLOC (2 * STAGE + 1024)

// Scratch (no allocation allowed)
__device__ float    g_partial[KSPL][BATCH * NEXP];   // 4 MB
__device__ float    g_imp[NEXP];
__device__ int      g_cnt[NEXP];
__device__ unsigned g_done;

// ---------------------------------------------------------------------------
// helpers
// ---------------------------------------------------------------------------
__device__ __forceinline__ uint32_t smem_to_u32(const void* p) {
    uint32_t a;
    asm("{ .reg .u64 t; cvta.to.shared.u64 t, %1; cvt.u32.u64 %0, t; }"
        : "=r"(a) : "l"(p));
    return a;
}

__device__ __forceinline__ void ldsm4(uint32_t* r, uint32_t addr) {
    asm volatile("ldmatrix.sync.aligned.m8n8.x4.shared.b16 {%0,%1,%2,%3}, [%4];"
                 : "=r"(r[0]), "=r"(r[1]), "=r"(r[2]), "=r"(r[3]) : "r"(addr));
}

__device__ __forceinline__ void mma16816(float* d, const uint32_t* a,
                                         const uint32_t* b) {
    asm volatile(
        "mma.sync.aligned.m16n8k16.row.col.f32.bf16.bf16.f32 "
        "{%0,%1,%2,%3}, {%4,%5,%6,%7}, {%8,%9}, {%0,%1,%2,%3};"
        : "+f"(d[0]), "+f"(d[1]), "+f"(d[2]), "+f"(d[3])
        : "r"(a[0]), "r"(a[1]), "r"(a[2]), "r"(a[3]), "r"(b[0]), "r"(b[1]));
}

// fp32 -> 3x bf16 split: h + m + l reproduces x to ~2^-26 relative
__device__ __forceinline__ uint32_t pack_bf16(float lo, float hi) {
    uint32_t r;
    asm("cvt.rn.bf16x2.f32 %0, %1, %2;" : "=r"(r) : "f"(hi), "f"(lo));
    return r;
}
__device__ __forceinline__ void split3(float x, float y,
                                       uint32_t& h, uint32_t& m, uint32_t& l) {
    h = pack_bf16(x, y);
    float hx = __uint_as_float(h << 16);
    float hy = __uint_as_float(h & 0xffff0000u);
    float rx = x - hx, ry = y - hy;
    m = pack_bf16(rx, ry);
    float mx = __uint_as_float(m << 16);
    float my = __uint_as_float(m & 0xffff0000u);
    l = pack_bf16(rx - mx, ry - my);
}
__device__ __forceinline__ void sts64(uint32_t addr, uint32_t a, uint32_t b) {
    asm volatile("st.shared.v2.b32 [%0], {%1, %2};"
                 :: "r"(addr), "r"(a), "r"(b) : "memory");
}

// ---------------------------------------------------------------------------
// Kernel 1: HMMA logits GEMM, fp32 emulated with bf16 3-split (6 products).
// D[128,64] per (m-tile, k-split). 256 threads = 8 warps = 4(M) x 2(N).
// ---------------------------------------------------------------------------
__global__ void __launch_bounds__(256, 1)
gemm_tc(const float* __restrict__ hs, const float* __restrict__ gw) {
    extern __shared__ char smem_raw[];
    const uint32_t sb = (smem_to_u32(smem_raw) + 1023u) & ~1023u;

    const int tid  = threadIdx.x;
    const int wid  = tid >> 5;
    const int lane = tid & 31;
    const int m0   = blockIdx.x * BM;
    const int sp   = blockIdx.y;
    const int k0   = sp * KHALF;

    // fold accumulator resets in (router runs after us in-stream)
    if (blockIdx.x == 0 && sp == 0 && tid < NEXP) {
        g_imp[tid] = 0.0f; g_cnt[tid] = 0;
        if (tid == 0) g_done = 0u;
    }

    // ---- f32 staging in regs ----
    float4 ar[8], br[4];
#define LOAD_A(t) do {                                                        \
    int kk = k0 + (t) * KT;                                                   \
    _Pragma("unroll")                                                         \
    for (int i = 0; i < 8; i++) {                                             \
        int lin = tid + i * 256; int row = lin >> 4; int c4 = lin & 15;       \
        ar[i] = *(const float4*)(hs + (size_t)(m0 + row) * ROWSTR + kk + c4 * 4); \
    } } while (0)
#define LOAD_B(t) do {                                                        \
    int kk = k0 + (t) * KT;                                                   \
    _Pragma("unroll")                                                         \
    for (int i = 0; i < 4; i++) {                                             \
        int lin = tid + i * 256; int row = lin >> 4; int c4 = lin & 15;       \
        br[i] = *(const float4*)(gw + (size_t)row * HID + kk + c4 * 4);       \
    } } while (0)

    LOAD_A(0); LOAD_B(0);

    // ---- per-warp ldmatrix base addresses (unswizzled) + swizzle masks ----
    const int mrow = (wid & 3) * 32;       // warp M offset within 128
    const int nrow = (wid >> 2) * 32;      // warp N offset within 64

    uint32_t abase[2], amask[2];
#pragma unroll
    for (int mt = 0; mt < 2; mt++) {
        int row = mrow + mt * 16 + (lane & 15);
        abase[mt] = (uint32_t)(row * 128 + (lane >> 4) * 16);
        amask[mt] = (uint32_t)((row & 7) << 4);
    }
    uint32_t bbase[2], bmask[2];
#pragma unroll
    for (int nt = 0; nt < 2; nt++) {
        int mat = lane >> 3, r = lane & 7;
        int n  = nrow + nt * 16 + (mat >> 1) * 8 + r;
        int kb = (mat & 1) * 16;
        bbase[nt] = (uint32_t)(n * 128 + kb);
        bmask[nt] = (uint32_t)((n & 7) << 4);
    }

    float acc[2][4][4];
#pragma unroll
    for (int a = 0; a < 2; a++)
#pragma unroll
        for (int b = 0; b < 4; b++)
#pragma unroll
            for (int c = 0; c < 4; c++) acc[a][b][c] = 0.0f;

    const int pa[6] = {0, 0, 1, 0, 2, 1};   // hh, hm, mh, hl, lh, mm
    const int pb[6] = {0, 1, 0, 2, 0, 1};

    for (int t = 0; t < NT; t++) {
        const uint32_t stg   = sb + (uint32_t)(t & 1) * STAGE;
        const uint32_t aBase = stg;
        const uint32_t bBase = stg + ABUF;

        // convert + swizzled store: A (8 float4 -> 3 planes)
#pragma unroll
        for (int i = 0; i < 8; i++) {
            int lin = tid + i * 256; int row = lin >> 4; int c4 = lin & 15;
            uint32_t off = (uint32_t)(row * 128 + c4 * 8);
            uint32_t sw  = off ^ ((off >> 3) & 0x70u);
            uint32_t h0, mm0, l0, h1, mm1, l1;
            split3(ar[i].x, ar[i].y, h0, mm0, l0);
            split3(ar[i].z, ar[i].w, h1, mm1, l1);
            sts64(aBase + sw,            h0,  h1);
            sts64(aBase + A_PL + sw,     mm0, mm1);
            sts64(aBase + 2 * A_PL + sw, l0,  l1);
        }
        // convert + swizzled store: B
#pragma unroll
        for (int i = 0; i < 4; i++) {
            int lin = tid + i * 256; int row = lin >> 4; int c4 = lin & 15;
            uint32_t off = (uint32_t)(row * 128 + c4 * 8);
            uint32_t sw  = off ^ ((off >> 3) & 0x70u);
            uint32_t h0, mm0, l0, h1, mm1, l1;
            split3(br[i].x, br[i].y, h0, mm0, l0);
            split3(br[i].z, br[i].w, h1, mm1, l1);
            sts64(bBase + sw,            h0,  h1);
            sts64(bBase + B_PL + sw,     mm0, mm1);
            sts64(bBase + 2 * B_PL + sw, l0,  l1);
        }
        __syncthreads();

        // prefetch next tile's f32 (overlaps with MMA below)
        if (t + 1 < NT) { LOAD_A(t + 1); LOAD_B(t + 1); }

        // compute: 4 k16 chunks x (12 ldmatrix.x4 + 48 mma)
#pragma unroll
        for (int kc = 0; kc < 4; kc++) {
            uint32_t af[3][2][4];
            uint32_t bf[3][2][4];
#pragma unroll
            for (int p = 0; p < 3; p++) {
#pragma unroll
                for (int mt = 0; mt < 2; mt++)
                    ldsm4(af[p][mt],
                          aBase + p * A_PL + ((abase[mt] + kc * 32) ^ amask[mt]));
#pragma unroll
                for (int nt = 0; nt < 2; nt++)
                    ldsm4(bf[p][nt],
                          bBase + p * B_PL + ((bbase[nt] + kc * 32) ^ bmask[nt]));
            }
#pragma unroll
            for (int pr = 0; pr < 6; pr++) {
#pragma unroll
                for (int mt = 0; mt < 2; mt++) {
#pragma unroll
                    for (int nt = 0; nt < 2; nt++) {
                        mma16816(acc[mt][nt * 2 + 0], af[pa[pr]][mt], &bf[pb[pr]][nt][0]);
                        mma16816(acc[mt][nt * 2 + 1], af[pa[pr]][mt], &bf[pb[pr]][nt][2]);
                    }
                }
            }
        }
        __syncthreads();
    }

    // ---- epilogue: write warp's 32x32 f32 tile to split partials ----
    const int gr = m0 + mrow + (lane >> 2);
    const int gc = nrow + (lane & 3) * 2;
#pragma unroll
    for (int mt = 0; mt < 2; mt++) {
#pragma unroll
        for (int n8 = 0; n8 < 4; n8++) {
            int row = gr + mt * 16;
            int col = gc + n8 * 8;
            float2 v0 = make_float2(acc[mt][n8][0], acc[mt][n8][1]);
            float2 v1 = make_float2(acc[mt][n8][2], acc[mt][n8][3]);
            *(float2*)&g_partial[sp][(size_t)row * NEXP + col]       = v0;
            *(float2*)&g_partial[sp][(size_t)(row + 8) * NEXP + col] = v1;
        }
    }
#undef LOAD_A
#undef LOAD_B
}

// ---------------------------------------------------------------------------
// Kernel 2: warp-per-row softmax + top-8 + weights + importance/load counts,
// with the aux-loss finalize folded into the last block (ticket pattern).
// ---------------------------------------------------------------------------
__global__ void __launch_bounds__(256)
router_kernel(float* __restrict__ out) {
    __shared__ float s_imp[NEXP];
    __shared__ int   s_cnt[NEXP];
    __shared__ int   s_last;
    const int tid = threadIdx.x;
    if (tid < NEXP) { s_imp[tid] = 0.0f; s_cnt[tid] = 0; }
    __syncthreads();

    const int lane = tid & 31;
    const int row  = (blockIdx.x * blockDim.x + tid) >> 5;

    float l0 = 0.0f, l1 = 0.0f;
#pragma unroll
    for (int sp = 0; sp < KSPL; sp++) {
        const float* p = &g_partial[sp][(size_t)row * NEXP];
        l0 += p[lane];
        l1 += p[lane + 32];
    }

    float m = fmaxf(l0, l1);
#pragma unroll
    for (int off = 16; off; off >>= 1)
        m = fmaxf(m, __shfl_xor_sync(0xffffffffu, m, off));
    float p0 = __expf(l0 - m);
    float p1 = __expf(l1 - m);
    float sm = p0 + p1;
#pragma unroll
    for (int off = 16; off; off >>= 1)
        sm += __shfl_xor_sync(0xffffffffu, sm, off);
    float inv = 1.0f / sm;
    p0 *= inv;
    p1 *= inv;

    atomicAdd(&s_imp[lane], p0);
    atomicAdd(&s_imp[lane + 32], p1);

    bool sel0 = false, sel1 = false;
    float wsum = 0.0f, myv = 0.0f;
    int myi = 0;
#pragma unroll
    for (int it = 0; it < TOPK; it++) {
        float cv = sel0 ? -1.0f : p0;
        int   ci = lane;
        if (!sel1 && p1 > cv) { cv = p1; ci = lane + 32; }
#pragma unroll
        for (int off = 16; off; off >>= 1) {
            float ov = __shfl_xor_sync(0xffffffffu, cv, off);
            int   oi = __shfl_xor_sync(0xffffffffu, ci, off);
            if (ov > cv || (ov == cv && oi < ci)) { cv = ov; ci = oi; }
        }
        wsum += cv;
        if (ci == lane)           sel0 = true;
        else if (ci == lane + 32) sel1 = true;
        if (lane == it) { myv = cv; myi = ci; }
        if (lane == 0)  atomicAdd(&s_cnt[ci], 1);
    }

    float invw = 1.0f / fmaxf(wsum, 1e-8f);
    if (lane < TOPK) {
        out[(size_t)row * TOPK + lane] = (float)myi;
        out[(size_t)BATCH * TOPK + (size_t)row * TOPK + lane] = myv * invw;
    }

    __syncthreads();
    if (tid < NEXP) {
        atomicAdd(&g_imp[tid], s_imp[tid]);
        atomicAdd(&g_cnt[tid], s_cnt[tid]);
        __threadfence();
    }
    __syncthreads();
    if (tid == 0) {
        unsigned tk = atomicAdd(&g_done, 1u);
        s_last = (tk == gridDim.x - 1) ? 1 : 0;
    }
    __syncthreads();

    if (s_last) {
        __shared__ float red[NEXP];
        if (tid < NEXP) {
            float vi = *(volatile float*)&g_imp[tid];
            int   ci = *(volatile int*)&g_cnt[tid];
            red[tid] = (float)NEXP * (vi / (float)BATCH) *
                       ((float)ci / (float)(BATCH * TOPK));
        }
        __syncthreads();
        if (tid == 0) {
            float s = 0.0f;
#pragma unroll
            for (int i = 0; i < NEXP; i++) s += red[i];
            out[(size_t)2 * BATCH * TOPK] = s;
        }
    }
}

// ---------------------------------------------------------------------------
extern "C" void kernel_launch(void* const* d_in, const int* in_sizes, int n_in,
                              void* d_out, int out_size) {
    const float* hs  = (const float*)d_in[0];
    const float* gw  = (const float*)d_in[1];
    float*       out = (float*)d_out;

    cudaFuncSetAttribute(gemm_tc, cudaFuncAttributeMaxDynamicSharedMemorySize,
                         SM_ALLOC);
    gemm_tc<<<dim3(BATCH / BM, KSPL), 256, SM_ALLOC>>>(hs, gw);
    router_kernel<<<(BATCH * 32) / 256, 256>>>(out);
}